// round 3
// baseline (speedup 1.0000x reference)
#include <cuda_runtime.h>
#include <mma.h>
#include <cstddef>

using namespace nvcuda;

// Problem dimensions (fixed by the reference).
#define D_DIM 1024
#define M_DIM 512
#define C_DIM 256
#define B_DIM 8192

// ---------------------------------------------------------------------------
// Scratch (static device globals; allocation-free, graph-safe).
// ---------------------------------------------------------------------------
__device__ alignas(16) float g_SP[D_DIM * B_DIM];     // predicted state  [D,B]
__device__ alignas(16) float g_INNOV[M_DIM * B_DIM];  // innovation       [M,B]
__device__ alignas(16) float g_T1[D_DIM * D_DIM];     // F @ state_cov
__device__ alignas(16) float g_covp[D_DIM * D_DIM];   // predicted cov
__device__ alignas(16) float g_HC[M_DIM * D_DIM];     // H @ cov_p
__device__ alignas(16) float g_S[M_DIM * M_DIM];      // innovation cov
__device__ alignas(16) float g_X1[M_DIM * M_DIM];     // Newton-Schulz ping
__device__ alignas(16) float g_X2[M_DIM * M_DIM];     // Newton-Schulz pong
__device__ alignas(16) float g_Y[M_DIM * M_DIM];      // S @ X
__device__ alignas(16) float g_CHT[D_DIM * M_DIM];    // cov_p @ H^T
__device__ alignas(16) float g_K[D_DIM * M_DIM];      // Kalman gain
__device__ alignas(16) float g_KH[D_DIM * D_DIM];     // K @ H
__device__ alignas(16) float g_norms[2];              // ||S||_inf

// ---------------------------------------------------------------------------
// TF32 tensor-core GEMM with 3xTF32 error compensation:
//   C = alpha * op(A) @ op(B) + beta * P
//   A is [M,K] row-major.
//   TB=false: B is [K,N] row-major.  TB=true: B is [N,K] row-major (B^T used).
//   P may be nullptr. M%BM==0, N%BN==0, K%BK==0 (holds for every call here).
//
// Each fp32 operand is split x = hi + lo with hi = tf32(x), lo = tf32(x - hi);
// acc += Ahi*Bhi + Alo*Bhi + Ahi*Blo  (lo*lo dropped: ~2^-22 relative error,
// i.e. fp32-equivalent accuracy at 3x tensor flops).
//
// Pipeline: register prefetch of tile k+1 while computing tile k from shared;
// two smem buffers, one __syncthreads per k-step.
// ---------------------------------------------------------------------------
template <int BM, int BN, int BK, int WM, int WN, bool TB>
__global__ void __launch_bounds__((BM / WM) * (BN / WN) * 32)
gemm_tf32(const float* __restrict__ A, const float* __restrict__ B,
          const float* __restrict__ P, float* __restrict__ C,
          int M, int N, int K, float alpha, float beta) {
    constexpr int WARPS_M = BM / WM;
    constexpr int WARPS_N = BN / WN;
    constexpr int THREADS = WARPS_M * WARPS_N * 32;
    constexpr int MT = WM / 16;   // m16 tiles per warp (M)
    constexpr int NT = WN / 16;   // n16 tiles per warp (N)
    constexpr int BKP = BK + 4;   // padded lds (20 floats: rows 16B-aligned)
    constexpr int BNP = BN + 4;
    constexpr int NA4 = (BM * BK / 4) / THREADS;  // float4 A-loads per thread
    constexpr int NB4 = (BK * BN / 4) / THREADS;  // float4 B-loads per thread
    static_assert(NA4 * THREADS * 4 == BM * BK, "A tile coverage");
    static_assert(NB4 * THREADS * 4 == BK * BN, "B tile coverage");
    static_assert(BK % 8 == 0, "BK must be a multiple of the k8 mma step");

    __shared__ float As[2][BM][BKP];  // [m][k] row-major
    __shared__ float Bs[2][BK][BNP];  // [k][n] row-major (post-transpose if TB)

    const int tid    = threadIdx.x;
    const int warpId = tid / 32;
    const int wm     = warpId / WARPS_N;
    const int wn     = warpId % WARPS_N;
    const int row0   = blockIdx.y * BM;
    const int col0   = blockIdx.x * BN;

    float4 pa[NA4], pb[NB4];

    auto loadA = [&](int k0) {
#pragma unroll
        for (int t = 0; t < NA4; t++) {
            int idx = tid + t * THREADS;
            int r   = idx / (BK / 4);
            int kq  = idx % (BK / 4);
            pa[t] = *reinterpret_cast<const float4*>(
                &A[(size_t)(row0 + r) * K + k0 + kq * 4]);
        }
    };
    auto loadB = [&](int k0) {
        if constexpr (!TB) {
#pragma unroll
            for (int t = 0; t < NB4; t++) {
                int idx = tid + t * THREADS;
                int kk  = idx / (BN / 4);
                int nq  = idx % (BN / 4);
                pb[t] = *reinterpret_cast<const float4*>(
                    &B[(size_t)(k0 + kk) * N + col0 + nq * 4]);
            }
        } else {
#pragma unroll
            for (int t = 0; t < NB4; t++) {
                int idx = tid + t * THREADS;
                int n   = idx / (BK / 4);
                int kq  = idx % (BK / 4);
                pb[t] = *reinterpret_cast<const float4*>(
                    &B[(size_t)(col0 + n) * K + k0 + kq * 4]);
            }
        }
    };
    auto storeA = [&](int buf) {
#pragma unroll
        for (int t = 0; t < NA4; t++) {
            int idx = tid + t * THREADS;
            int r   = idx / (BK / 4);
            int kq  = idx % (BK / 4);
            *reinterpret_cast<float4*>(&As[buf][r][kq * 4]) = pa[t];
        }
    };
    auto storeB = [&](int buf) {
        if constexpr (!TB) {
#pragma unroll
            for (int t = 0; t < NB4; t++) {
                int idx = tid + t * THREADS;
                int kk  = idx / (BN / 4);
                int nq  = idx % (BN / 4);
                *reinterpret_cast<float4*>(&Bs[buf][kk][nq * 4]) = pb[t];
            }
        } else {
#pragma unroll
            for (int t = 0; t < NB4; t++) {
                int idx = tid + t * THREADS;
                int n   = idx / (BK / 4);
                int kq  = idx % (BK / 4);
                Bs[buf][kq * 4 + 0][n] = pb[t].x;
                Bs[buf][kq * 4 + 1][n] = pb[t].y;
                Bs[buf][kq * 4 + 2][n] = pb[t].z;
                Bs[buf][kq * 4 + 3][n] = pb[t].w;
            }
        }
    };

    using FragA = wmma::fragment<wmma::matrix_a, 16, 16, 8,
                                 wmma::precision::tf32, wmma::row_major>;
    using FragB = wmma::fragment<wmma::matrix_b, 16, 16, 8,
                                 wmma::precision::tf32, wmma::row_major>;
    using FragC = wmma::fragment<wmma::accumulator, 16, 16, 8, float>;

    FragC acc[MT][NT];
#pragma unroll
    for (int i = 0; i < MT; i++)
#pragma unroll
        for (int j = 0; j < NT; j++) wmma::fill_fragment(acc[i][j], 0.0f);

    // ---- prologue: fill buffer 0 ----
    loadA(0);
    loadB(0);
    storeA(0);
    storeB(0);
    __syncthreads();

    int buf = 0;
    for (int k0 = 0; k0 < K; k0 += BK) {
        const bool has_next = (k0 + BK < K);
        if (has_next) {  // issue next tile's global loads early
            loadA(k0 + BK);
            loadB(k0 + BK);
        }

        // ---- tensor-core compute on smem[buf] ----
#pragma unroll
        for (int ks = 0; ks < BK; ks += 8) {
            FragB bhi[NT], blo[NT];
#pragma unroll
            for (int j = 0; j < NT; j++) {
                FragB braw;
                wmma::load_matrix_sync(braw, &Bs[buf][ks][wn * WN + j * 16], BNP);
#pragma unroll
                for (int e = 0; e < braw.num_elements; e++) {
                    float v = braw.x[e];
                    float h = wmma::__float_to_tf32(v);
                    bhi[j].x[e] = h;
                    blo[j].x[e] = wmma::__float_to_tf32(v - h);
                }
            }
#pragma unroll
            for (int i = 0; i < MT; i++) {
                FragA araw, ahi, alo;
                wmma::load_matrix_sync(araw, &As[buf][wm * WM + i * 16][ks], BKP);
#pragma unroll
                for (int e = 0; e < araw.num_elements; e++) {
                    float v = araw.x[e];
                    float h = wmma::__float_to_tf32(v);
                    ahi.x[e] = h;
                    alo.x[e] = wmma::__float_to_tf32(v - h);
                }
#pragma unroll
                for (int j = 0; j < NT; j++) {
                    wmma::mma_sync(acc[i][j], ahi, bhi[j], acc[i][j]);
                    wmma::mma_sync(acc[i][j], alo, bhi[j], acc[i][j]);
                    wmma::mma_sync(acc[i][j], ahi, blo[j], acc[i][j]);
                }
            }
        }

        if (has_next) {  // commit prefetched tile to the other buffer
            storeA(1 - buf);
            storeB(1 - buf);
            __syncthreads();
            buf ^= 1;
        }
    }

    // ---- epilogue: C = alpha*acc + beta*P ----
#pragma unroll
    for (int i = 0; i < MT; i++) {
#pragma unroll
        for (int j = 0; j < NT; j++) {
            const int r = row0 + wm * WM + i * 16;
            const int c = col0 + wn * WN + j * 16;
            if (P != nullptr) {
                FragC pf;
                wmma::load_matrix_sync(pf, &P[(size_t)r * N + c], N,
                                       wmma::mem_row_major);
#pragma unroll
                for (int e = 0; e < pf.num_elements; e++)
                    acc[i][j].x[e] = alpha * acc[i][j].x[e] + beta * pf.x[e];
            } else {
#pragma unroll
                for (int e = 0; e < acc[i][j].num_elements; e++)
                    acc[i][j].x[e] *= alpha;
            }
            wmma::store_matrix_sync(&C[(size_t)r * N + c], acc[i][j], N,
                                    wmma::mem_row_major);
        }
    }
}

// ---------------------------------------------------------------------------
// ||S||_inf (max abs row sum) for 512x512 S.
// ---------------------------------------------------------------------------
__global__ void norms_kernel(const float* __restrict__ S, float* __restrict__ norms) {
    const int i = threadIdx.x;  // 512 threads, 1 block
    float rs = 0.0f;
    for (int j = 0; j < M_DIM; j++) rs += fabsf(S[(size_t)i * M_DIM + j]);
    __shared__ float sr[M_DIM];
    sr[i] = rs;
    __syncthreads();
    for (int s = M_DIM / 2; s > 0; s >>= 1) {
        if (i < s) sr[i] = fmaxf(sr[i], sr[i + s]);
        __syncthreads();
    }
    if (i == 0) norms[0] = sr[0];
}

// X0 = I / ||S||_inf  (S is near-SPD: Re(lambda) >> |asym|, so rho(I-X0 S)<1).
__global__ void init_x_kernel(const float* __restrict__ norms,
                              float* __restrict__ X) {
    const int idx = blockIdx.x * blockDim.x + threadIdx.x;
    if (idx >= M_DIM * M_DIM) return;
    const int i = idx / M_DIM;
    const int j = idx % M_DIM;
    X[idx] = (i == j) ? (1.0f / norms[0]) : 0.0f;
}

// ---------------------------------------------------------------------------
// Launch helpers.
//   Big (N=8192 panels): 128x128 tile, 8 warps, warp tile 64x32.
//   Small (dims <= 1024): 64x64 tile, 4 warps, warp tile 32x32.
// ---------------------------------------------------------------------------
static inline void g128_nn(const float* A, const float* B, const float* P, float* C,
                           int M, int N, int K, float alpha, float beta) {
    dim3 grid(N / 128, M / 128), block(256);
    gemm_tf32<128, 128, 16, 64, 32, false><<<grid, block>>>(A, B, P, C, M, N, K, alpha, beta);
}
static inline void g64_nn(const float* A, const float* B, const float* P, float* C,
                          int M, int N, int K, float alpha, float beta) {
    dim3 grid(N / 64, M / 64), block(128);
    gemm_tf32<64, 64, 16, 32, 32, false><<<grid, block>>>(A, B, P, C, M, N, K, alpha, beta);
}
static inline void g64_nt(const float* A, const float* B, const float* P, float* C,
                          int M, int N, int K, float alpha, float beta) {
    dim3 grid(N / 64, M / 64), block(128);
    gemm_tf32<64, 64, 16, 32, 32, true><<<grid, block>>>(A, B, P, C, M, N, K, alpha, beta);
}

// ---------------------------------------------------------------------------
// kernel_launch: full Kalman step.
// Inputs (metadata order): state, state_cov, meas, control, F, Q, Bc, H, R
// Output: [state_n (D*B) | cov_n (D*D)]
// ---------------------------------------------------------------------------
extern "C" void kernel_launch(void* const* d_in, const int* in_sizes, int n_in,
                              void* d_out, int out_size) {
    const float* state     = (const float*)d_in[0];  // [D,B]
    const float* state_cov = (const float*)d_in[1];  // [D,D]
    const float* meas      = (const float*)d_in[2];  // [M,B]
    const float* control   = (const float*)d_in[3];  // [C,B]
    const float* F         = (const float*)d_in[4];  // [D,D]
    const float* Q         = (const float*)d_in[5];  // [D,D]
    const float* Bc        = (const float*)d_in[6];  // [D,C]
    const float* H         = (const float*)d_in[7];  // [M,D]
    const float* R         = (const float*)d_in[8];  // [M,M]

    float* out_state = (float*)d_out;
    float* out_cov   = out_state + (size_t)D_DIM * B_DIM;

    float *SP, *INNOV, *T1, *covp, *HC, *S, *X1, *X2, *Y, *CHT, *Kg, *KH, *norms;
    cudaGetSymbolAddress((void**)&SP, g_SP);
    cudaGetSymbolAddress((void**)&INNOV, g_INNOV);
    cudaGetSymbolAddress((void**)&T1, g_T1);
    cudaGetSymbolAddress((void**)&covp, g_covp);
    cudaGetSymbolAddress((void**)&HC, g_HC);
    cudaGetSymbolAddress((void**)&S, g_S);
    cudaGetSymbolAddress((void**)&X1, g_X1);
    cudaGetSymbolAddress((void**)&X2, g_X2);
    cudaGetSymbolAddress((void**)&Y, g_Y);
    cudaGetSymbolAddress((void**)&CHT, g_CHT);
    cudaGetSymbolAddress((void**)&Kg, g_K);
    cudaGetSymbolAddress((void**)&KH, g_KH);
    cudaGetSymbolAddress((void**)&norms, g_norms);

    // ---- prediction ----
    // SP = F @ state
    g128_nn(F, state, nullptr, SP, D_DIM, B_DIM, D_DIM, 1.0f, 0.0f);
    // SP += Bc @ control
    g128_nn(Bc, control, SP, SP, D_DIM, B_DIM, C_DIM, 1.0f, 1.0f);
    // T1 = F @ state_cov
    g64_nn(F, state_cov, nullptr, T1, D_DIM, D_DIM, D_DIM, 1.0f, 0.0f);
    // cov_p = T1 @ F^T + Q
    g64_nt(T1, F, Q, covp, D_DIM, D_DIM, D_DIM, 1.0f, 1.0f);

    // ---- correction ----
    // innovation = meas - H @ SP
    g128_nn(H, SP, meas, INNOV, M_DIM, B_DIM, D_DIM, -1.0f, 1.0f);
    // HC = H @ cov_p
    g64_nn(H, covp, nullptr, HC, M_DIM, D_DIM, D_DIM, 1.0f, 0.0f);
    // S = HC @ H^T + R
    g64_nt(HC, H, R, S, M_DIM, M_DIM, D_DIM, 1.0f, 1.0f);

    // ---- S^{-1} via Newton-Schulz:  X <- X (2I - S X) = 2X - X(SX) ----
    norms_kernel<<<1, M_DIM>>>(S, norms);
    {
        int total = M_DIM * M_DIM;
        init_x_kernel<<<(total + 255) / 256, 256>>>(norms, X1);
    }
    float* X  = X1;
    float* Xn = X2;
    for (int it = 0; it < 13; ++it) {
        // Y = S @ X
        g64_nn(S, X, nullptr, Y, M_DIM, M_DIM, M_DIM, 1.0f, 0.0f);
        // Xn = 2*X - X @ Y
        g64_nn(X, Y, X, Xn, M_DIM, M_DIM, M_DIM, -1.0f, 2.0f);
        float* t = X; X = Xn; Xn = t;
    }
    const float* Sinv = X;

    // CHT = cov_p @ H^T
    g64_nt(covp, H, nullptr, CHT, D_DIM, M_DIM, D_DIM, 1.0f, 0.0f);
    // K = CHT @ Sinv
    g64_nn(CHT, Sinv, nullptr, Kg, D_DIM, M_DIM, M_DIM, 1.0f, 0.0f);

    // state_n = SP + K @ innovation   -> out_state
    g128_nn(Kg, INNOV, SP, out_state, D_DIM, B_DIM, M_DIM, 1.0f, 1.0f);

    // KH = K @ H
    g64_nn(Kg, H, nullptr, KH, D_DIM, D_DIM, M_DIM, 1.0f, 0.0f);
    // cov_n = cov_p - KH @ cov_p      -> out_cov
    g64_nn(KH, covp, covp, out_cov, D_DIM, D_DIM, D_DIM, -1.0f, 1.0f);
}

// round 9
// speedup vs baseline: 1.4211x; 1.4211x over previous
#include <cuda_runtime.h>
#include <mma.h>
#include <cstddef>

using namespace nvcuda;

// Problem dimensions (fixed by the reference).
#define D_DIM 1024
#define M_DIM 512
#define C_DIM 256
#define B_DIM 8192

// ---------------------------------------------------------------------------
// Scratch (static device globals; allocation-free, graph-safe).
// ---------------------------------------------------------------------------
__device__ alignas(16) float g_SP[D_DIM * B_DIM];     // predicted state  [D,B]
__device__ alignas(16) float g_INNOV[M_DIM * B_DIM];  // innovation       [M,B]
__device__ alignas(16) float g_T1[D_DIM * D_DIM];     // F @ state_cov
__device__ alignas(16) float g_covp[D_DIM * D_DIM];   // predicted cov
__device__ alignas(16) float g_HC[M_DIM * D_DIM];     // H @ cov_p
__device__ alignas(16) float g_S[M_DIM * M_DIM];      // innovation cov
__device__ alignas(16) float g_X1[M_DIM * M_DIM];     // Newton-Schulz ping
__device__ alignas(16) float g_X2[M_DIM * M_DIM];     // Newton-Schulz pong
__device__ alignas(16) float g_Y[M_DIM * M_DIM];      // S @ X
__device__ alignas(16) float g_CHT[D_DIM * M_DIM];    // cov_p @ H^T
__device__ alignas(16) float g_K[D_DIM * M_DIM];      // Kalman gain
__device__ alignas(16) float g_norms[2];              // ||S||_1

// ---------------------------------------------------------------------------
// TF32 tensor-core GEMM with 3xTF32 error compensation:
//   C = alpha * op(A) @ op(B) + beta * P
//   A is [M,K] row-major.
//   TB=false: B is [K,N] row-major.  TB=true: B is [N,K] row-major (B^T used).
//   P may be nullptr. M%BM==0, N%BN==0, K%BK==0 (holds for every call here).
//
// Each fp32 operand is split x = hi + lo with hi = tf32(x), lo = tf32(x - hi);
// acc += Ahi*Bhi + Alo*Bhi + Ahi*Blo  (lo*lo dropped: ~2^-22 relative error,
// i.e. fp32-equivalent accuracy at 3x tensor flops).
//
// Pipeline: register prefetch of tile k+1 while computing tile k from shared;
// two smem buffers, one __syncthreads per k-step.
// ---------------------------------------------------------------------------
template <int BM, int BN, int BK, int WM, int WN, bool TB>
__global__ void __launch_bounds__((BM / WM) * (BN / WN) * 32)
gemm_tf32(const float* __restrict__ A, const float* __restrict__ B,
          const float* __restrict__ P, float* __restrict__ C,
          int M, int N, int K, float alpha, float beta) {
    constexpr int WARPS_M = BM / WM;
    constexpr int WARPS_N = BN / WN;
    constexpr int THREADS = WARPS_M * WARPS_N * 32;
    constexpr int MT = WM / 16;   // m16 tiles per warp (M)
    constexpr int NT = WN / 16;   // n16 tiles per warp (N)
    constexpr int BKP = BK + 4;   // padded lds (rows stay 16B-aligned)
    constexpr int BNP = BN + 4;
    constexpr int NA4 = (BM * BK / 4) / THREADS;  // float4 A-loads per thread
    constexpr int NB4 = (BK * BN / 4) / THREADS;  // float4 B-loads per thread
    static_assert(NA4 * THREADS * 4 == BM * BK, "A tile coverage");
    static_assert(NB4 * THREADS * 4 == BK * BN, "B tile coverage");
    static_assert(BK % 8 == 0, "BK must be a multiple of the k8 mma step");

    __shared__ float As[2][BM][BKP];  // [m][k] row-major
    __shared__ float Bs[2][BK][BNP];  // [k][n] row-major (post-transpose if TB)

    const int tid    = threadIdx.x;
    const int warpId = tid / 32;
    const int wm     = warpId / WARPS_N;
    const int wn     = warpId % WARPS_N;
    const int row0   = blockIdx.y * BM;
    const int col0   = blockIdx.x * BN;

    float4 pa[NA4], pb[NB4];

    auto loadA = [&](int k0) {
#pragma unroll
        for (int t = 0; t < NA4; t++) {
            int idx = tid + t * THREADS;
            int r   = idx / (BK / 4);
            int kq  = idx % (BK / 4);
            pa[t] = *reinterpret_cast<const float4*>(
                &A[(size_t)(row0 + r) * K + k0 + kq * 4]);
        }
    };
    auto loadB = [&](int k0) {
        if constexpr (!TB) {
#pragma unroll
            for (int t = 0; t < NB4; t++) {
                int idx = tid + t * THREADS;
                int kk  = idx / (BN / 4);
                int nq  = idx % (BN / 4);
                pb[t] = *reinterpret_cast<const float4*>(
                    &B[(size_t)(k0 + kk) * N + col0 + nq * 4]);
            }
        } else {
#pragma unroll
            for (int t = 0; t < NB4; t++) {
                int idx = tid + t * THREADS;
                int n   = idx / (BK / 4);
                int kq  = idx % (BK / 4);
                pb[t] = *reinterpret_cast<const float4*>(
                    &B[(size_t)(col0 + n) * K + k0 + kq * 4]);
            }
        }
    };
    auto storeA = [&](int buf) {
#pragma unroll
        for (int t = 0; t < NA4; t++) {
            int idx = tid + t * THREADS;
            int r   = idx / (BK / 4);
            int kq  = idx % (BK / 4);
            *reinterpret_cast<float4*>(&As[buf][r][kq * 4]) = pa[t];
        }
    };
    auto storeB = [&](int buf) {
        if constexpr (!TB) {
#pragma unroll
            for (int t = 0; t < NB4; t++) {
                int idx = tid + t * THREADS;
                int kk  = idx / (BN / 4);
                int nq  = idx % (BN / 4);
                *reinterpret_cast<float4*>(&Bs[buf][kk][nq * 4]) = pb[t];
            }
        } else {
#pragma unroll
            for (int t = 0; t < NB4; t++) {
                int idx = tid + t * THREADS;
                int n   = idx / (BK / 4);
                int kq  = idx % (BK / 4);
                Bs[buf][kq * 4 + 0][n] = pb[t].x;
                Bs[buf][kq * 4 + 1][n] = pb[t].y;
                Bs[buf][kq * 4 + 2][n] = pb[t].z;
                Bs[buf][kq * 4 + 3][n] = pb[t].w;
            }
        }
    };

    using FragA = wmma::fragment<wmma::matrix_a, 16, 16, 8,
                                 wmma::precision::tf32, wmma::row_major>;
    using FragB = wmma::fragment<wmma::matrix_b, 16, 16, 8,
                                 wmma::precision::tf32, wmma::row_major>;
    using FragC = wmma::fragment<wmma::accumulator, 16, 16, 8, float>;

    FragC acc[MT][NT];
#pragma unroll
    for (int i = 0; i < MT; i++)
#pragma unroll
        for (int j = 0; j < NT; j++) wmma::fill_fragment(acc[i][j], 0.0f);

    // ---- prologue: fill buffer 0 ----
    loadA(0);
    loadB(0);
    storeA(0);
    storeB(0);
    __syncthreads();

    int buf = 0;
    for (int k0 = 0; k0 < K; k0 += BK) {
        const bool has_next = (k0 + BK < K);
        if (has_next) {  // issue next tile's global loads early
            loadA(k0 + BK);
            loadB(k0 + BK);
        }

        // ---- tensor-core compute on smem[buf] ----
#pragma unroll
        for (int ks = 0; ks < BK; ks += 8) {
            FragB bhi[NT], blo[NT];
#pragma unroll
            for (int j = 0; j < NT; j++) {
                FragB braw;
                wmma::load_matrix_sync(braw, &Bs[buf][ks][wn * WN + j * 16], BNP);
#pragma unroll
                for (int e = 0; e < braw.num_elements; e++) {
                    float v = braw.x[e];
                    float h = wmma::__float_to_tf32(v);
                    bhi[j].x[e] = h;
                    blo[j].x[e] = wmma::__float_to_tf32(v - h);
                }
            }
#pragma unroll
            for (int i = 0; i < MT; i++) {
                FragA araw, ahi, alo;
                wmma::load_matrix_sync(araw, &As[buf][wm * WM + i * 16][ks], BKP);
#pragma unroll
                for (int e = 0; e < araw.num_elements; e++) {
                    float v = araw.x[e];
                    float h = wmma::__float_to_tf32(v);
                    ahi.x[e] = h;
                    alo.x[e] = wmma::__float_to_tf32(v - h);
                }
#pragma unroll
                for (int j = 0; j < NT; j++) {
                    wmma::mma_sync(acc[i][j], ahi, bhi[j], acc[i][j]);
                    wmma::mma_sync(acc[i][j], alo, bhi[j], acc[i][j]);
                    wmma::mma_sync(acc[i][j], ahi, blo[j], acc[i][j]);
                }
            }
        }

        if (has_next) {  // commit prefetched tile to the other buffer
            storeA(1 - buf);
            storeB(1 - buf);
            __syncthreads();
            buf ^= 1;
        }
    }

    // ---- epilogue: C = alpha*acc + beta*P ----
#pragma unroll
    for (int i = 0; i < MT; i++) {
#pragma unroll
        for (int j = 0; j < NT; j++) {
            const int r = row0 + wm * WM + i * 16;
            const int c = col0 + wn * WN + j * 16;
            if (P != nullptr) {
                FragC pf;
                wmma::load_matrix_sync(pf, &P[(size_t)r * N + c], N,
                                       wmma::mem_row_major);
#pragma unroll
                for (int e = 0; e < pf.num_elements; e++)
                    acc[i][j].x[e] = alpha * acc[i][j].x[e] + beta * pf.x[e];
            } else {
#pragma unroll
                for (int e = 0; e < acc[i][j].num_elements; e++)
                    acc[i][j].x[e] *= alpha;
            }
            wmma::store_matrix_sync(&C[(size_t)r * N + c], acc[i][j], N,
                                    wmma::mem_row_major);
        }
    }
}

// ---------------------------------------------------------------------------
// ||S||_1 (max abs column sum) for 512x512 S — coalesced: for fixed j, thread
// i reads S[j*M+i], consecutive addresses across the warp. Any induced norm
// >= rho(S) is a valid Newton-Schulz scaling.
// ---------------------------------------------------------------------------
__global__ void norms_kernel(const float* __restrict__ S, float* __restrict__ norms) {
    const int i = threadIdx.x;  // 512 threads, 1 block; thread i -> column i
    float cs = 0.0f;
    for (int j = 0; j < M_DIM; j++) cs += fabsf(S[(size_t)j * M_DIM + i]);
    __shared__ float sr[M_DIM];
    sr[i] = cs;
    __syncthreads();
    for (int s = M_DIM / 2; s > 0; s >>= 1) {
        if (i < s) sr[i] = fmaxf(sr[i], sr[i + s]);
        __syncthreads();
    }
    if (i == 0) norms[0] = sr[0];
}

// Analytic fold of Newton-Schulz iteration 1:
//   X0 = I/c  (c = ||S||_1)  =>  X1 = X0 (2I - S X0) = (2/c) I - S / c^2.
// Writing X1 directly replaces two serial 512^3 GEMM launches with one
// elementwise pass (exact same math). Convergence unchanged: rho(I - X0 S)<1
// since S is near-SPD (Re(lambda)>0) and c >= rho(S).
__global__ void init_x_kernel(const float* __restrict__ S,
                              const float* __restrict__ norms,
                              float* __restrict__ X) {
    const int idx = blockIdx.x * blockDim.x + threadIdx.x;
    if (idx >= M_DIM * M_DIM) return;
    const int i = idx / M_DIM;
    const int j = idx % M_DIM;
    const float c    = norms[0];
    const float inv  = 1.0f / c;
    const float inv2 = inv * inv;
    X[idx] = ((i == j) ? 2.0f * inv : 0.0f) - S[idx] * inv2;
}

// ---------------------------------------------------------------------------
// Launch helpers.
//   Big (N=8192 panels): 128x128x16 tile, 8 warps, warp tile 64x32.
//   Small (dims <= 1024): 64x64x32 tile, 8 warps, warp tile 32x16.
//   NS (512x512x512):     64x32x32 tile, 4 warps, warp tile 32x16.
//     512^2 output / (64x32) = 128 CTAs -> 86% SM coverage (vs 64 CTAs / 43%
//     with 64x64 tiles) on the 18-GEMM serial Newton-Schulz chain.
// ---------------------------------------------------------------------------
static inline void g128_nn(const float* A, const float* B, const float* P, float* C,
                           int M, int N, int K, float alpha, float beta,
                           cudaStream_t st) {
    dim3 grid(N / 128, M / 128), block(256);
    gemm_tf32<128, 128, 16, 64, 32, false><<<grid, block, 0, st>>>(A, B, P, C, M, N, K, alpha, beta);
}
static inline void g64_nn(const float* A, const float* B, const float* P, float* C,
                          int M, int N, int K, float alpha, float beta,
                          cudaStream_t st) {
    dim3 grid(N / 64, M / 64), block(256);
    gemm_tf32<64, 64, 32, 32, 16, false><<<grid, block, 0, st>>>(A, B, P, C, M, N, K, alpha, beta);
}
static inline void g64_nt(const float* A, const float* B, const float* P, float* C,
                          int M, int N, int K, float alpha, float beta,
                          cudaStream_t st) {
    dim3 grid(N / 64, M / 64), block(256);
    gemm_tf32<64, 64, 32, 32, 16, true><<<grid, block, 0, st>>>(A, B, P, C, M, N, K, alpha, beta);
}
static inline void gns_nn(const float* A, const float* B, const float* P, float* C,
                          int M, int N, int K, float alpha, float beta,
                          cudaStream_t st) {
    dim3 grid(N / 32, M / 64), block(128);
    gemm_tf32<64, 32, 32, 32, 16, false><<<grid, block, 0, st>>>(A, B, P, C, M, N, K, alpha, beta);
}

// ---------------------------------------------------------------------------
// kernel_launch: full Kalman step.
// Inputs (metadata order): state, state_cov, meas, control, F, Q, Bc, H, R
// Output: [state_n (D*B) | cov_n (D*D)]
//
// 3-stream fork-join schedule (capture-legal event fork/join):
//   s1:   SP -> SP+=Bc*u -> INNOV                (big GEMMs, independent)
//   main: T1 -> covp -> HC -> S -> NS -> K -> (join s1) state_n
//   s2:   (after covp) CHT      (after K) cov_n = covp - K @ HC
// CHT overlaps the serial NS chain; the cov_n tail overlaps state_n.
// cov_n uses the identity (I - K H) covp = covp - K (H covp) = covp - K@HC,
// reusing HC and eliminating the K@H GEMM entirely.
// ---------------------------------------------------------------------------
extern "C" void kernel_launch(void* const* d_in, const int* in_sizes, int n_in,
                              void* d_out, int out_size) {
    const float* state     = (const float*)d_in[0];  // [D,B]
    const float* state_cov = (const float*)d_in[1];  // [D,D]
    const float* meas      = (const float*)d_in[2];  // [M,B]
    const float* control   = (const float*)d_in[3];  // [C,B]
    const float* F         = (const float*)d_in[4];  // [D,D]
    const float* Q         = (const float*)d_in[5];  // [D,D]
    const float* Bc        = (const float*)d_in[6];  // [D,C]
    const float* H         = (const float*)d_in[7];  // [M,D]
    const float* R         = (const float*)d_in[8];  // [M,M]

    float* out_state = (float*)d_out;
    float* out_cov   = out_state + (size_t)D_DIM * B_DIM;

    float *SP, *INNOV, *T1, *covp, *HC, *S, *X1, *X2, *Y, *CHT, *Kg, *norms;
    cudaGetSymbolAddress((void**)&SP, g_SP);
    cudaGetSymbolAddress((void**)&INNOV, g_INNOV);
    cudaGetSymbolAddress((void**)&T1, g_T1);
    cudaGetSymbolAddress((void**)&covp, g_covp);
    cudaGetSymbolAddress((void**)&HC, g_HC);
    cudaGetSymbolAddress((void**)&S, g_S);
    cudaGetSymbolAddress((void**)&X1, g_X1);
    cudaGetSymbolAddress((void**)&X2, g_X2);
    cudaGetSymbolAddress((void**)&Y, g_Y);
    cudaGetSymbolAddress((void**)&CHT, g_CHT);
    cudaGetSymbolAddress((void**)&Kg, g_K);
    cudaGetSymbolAddress((void**)&norms, g_norms);

    // One-time stream/event setup (created on the first, non-captured
    // correctness call; reused identically every call — not a work guard).
    static cudaStream_t s1 = nullptr, s2 = nullptr;
    static cudaEvent_t ev_fork1 = nullptr, ev_state = nullptr,
                       ev_covp = nullptr, ev_cht = nullptr, ev_k = nullptr,
                       ev_cov = nullptr;
    if (s1 == nullptr) {
        cudaStreamCreateWithFlags(&s1, cudaStreamNonBlocking);
        cudaStreamCreateWithFlags(&s2, cudaStreamNonBlocking);
        cudaEventCreateWithFlags(&ev_fork1, cudaEventDisableTiming);
        cudaEventCreateWithFlags(&ev_state, cudaEventDisableTiming);
        cudaEventCreateWithFlags(&ev_covp, cudaEventDisableTiming);
        cudaEventCreateWithFlags(&ev_cht, cudaEventDisableTiming);
        cudaEventCreateWithFlags(&ev_k, cudaEventDisableTiming);
        cudaEventCreateWithFlags(&ev_cov, cudaEventDisableTiming);
    }
    cudaStream_t mn = 0;

    // ---- fork s1: state path (big GEMMs) ----
    cudaEventRecord(ev_fork1, mn);
    cudaStreamWaitEvent(s1, ev_fork1, 0);
    // SP = F @ state
    g128_nn(F, state, nullptr, SP, D_DIM, B_DIM, D_DIM, 1.0f, 0.0f, s1);
    // SP += Bc @ control
    g128_nn(Bc, control, SP, SP, D_DIM, B_DIM, C_DIM, 1.0f, 1.0f, s1);
    // innovation = meas - H @ SP
    g128_nn(H, SP, meas, INNOV, M_DIM, B_DIM, D_DIM, -1.0f, 1.0f, s1);
    cudaEventRecord(ev_state, s1);

    // ---- main: covariance path ----
    // T1 = F @ state_cov
    g64_nn(F, state_cov, nullptr, T1, D_DIM, D_DIM, D_DIM, 1.0f, 0.0f, mn);
    // cov_p = T1 @ F^T + Q
    g64_nt(T1, F, Q, covp, D_DIM, D_DIM, D_DIM, 1.0f, 1.0f, mn);
    cudaEventRecord(ev_covp, mn);

    // ---- fork s2: CHT = cov_p @ H^T (independent of the NS chain) ----
    cudaStreamWaitEvent(s2, ev_covp, 0);
    g64_nt(covp, H, nullptr, CHT, D_DIM, M_DIM, D_DIM, 1.0f, 0.0f, s2);
    cudaEventRecord(ev_cht, s2);

    // ---- main: HC -> S -> Newton-Schulz ----
    // HC = H @ cov_p
    g64_nn(H, covp, nullptr, HC, M_DIM, D_DIM, D_DIM, 1.0f, 0.0f, mn);
    // S = HC @ H^T + R
    g64_nt(HC, H, R, S, M_DIM, M_DIM, D_DIM, 1.0f, 1.0f, mn);

    // S^{-1} via Newton-Schulz:  X <- X (2I - S X) = 2X - X(SX).
    // Iteration 1 is folded analytically into init_x_kernel (X1 = 2/c I - S/c^2),
    // so 9 GEMM iterations here == 10 total.
    norms_kernel<<<1, M_DIM, 0, mn>>>(S, norms);
    {
        int total = M_DIM * M_DIM;
        init_x_kernel<<<(total + 255) / 256, 256, 0, mn>>>(S, norms, X1);
    }
    float* X  = X1;
    float* Xn = X2;
    for (int it = 0; it < 9; ++it) {
        // Y = S @ X
        gns_nn(S, X, nullptr, Y, M_DIM, M_DIM, M_DIM, 1.0f, 0.0f, mn);
        // Xn = 2*X - X @ Y
        gns_nn(X, Y, X, Xn, M_DIM, M_DIM, M_DIM, -1.0f, 2.0f, mn);
        float* t = X; X = Xn; Xn = t;
    }
    const float* Sinv = X;

    // ---- main: K = CHT @ Sinv (needs CHT from s2) ----
    cudaStreamWaitEvent(mn, ev_cht, 0);
    g64_nn(CHT, Sinv, nullptr, Kg, D_DIM, M_DIM, M_DIM, 1.0f, 0.0f, mn);
    cudaEventRecord(ev_k, mn);

    // ---- s2: covariance tail (overlaps state_n on main) ----
    cudaStreamWaitEvent(s2, ev_k, 0);
    // cov_n = cov_p - K @ HC   -> out_cov   (identity: (I-KH)covp = covp - K@HC)
    g64_nn(Kg, HC, covp, out_cov, D_DIM, D_DIM, M_DIM, -1.0f, 1.0f, s2);
    cudaEventRecord(ev_cov, s2);

    // ---- main: state_n = SP + K @ innovation -> out_state (needs s1) ----
    cudaStreamWaitEvent(mn, ev_state, 0);
    g128_nn(Kg, INNOV, SP, out_state, D_DIM, B_DIM, M_DIM, 1.0f, 1.0f, mn);

    // ---- final join: cov path back into the origin stream ----
    cudaStreamWaitEvent(mn, ev_cov, 0);
}